// round 3
// baseline (speedup 1.0000x reference)
#include <cuda_runtime.h>

// Smoother: out = max(pred, (moving_sum_501(reflect_pad(pred)) + bias) / 501)
// pred: [B=8, T=16384, C=128] fp32, bias: [1] fp32, out: same shape as pred.
//
// Strategy: register-resident sliding window sum along T, one thread per
// channel, one block per (batch, 256-row T segment). Leading/trailing loads
// are coalesced (threadIdx.x = channel, C contiguous). Trailing + mid streams
// trail the lead by <=501 rows (~2MB chip-wide working set) -> L2 hits.

#define Bn   8
#define Tn   16384
#define Cn   128
#define Kn   501
#define Pn   250
#define SEG  256
#define NSEG (Tn / SEG)   // 64

__device__ __forceinline__ int refl(int k) {
    // jnp.pad(..., mode="reflect"): no edge repeat
    if (k < 0) k = -k;
    if (k >= Tn) k = 2 * Tn - 2 - k;
    return k;
}

__global__ void __launch_bounds__(Cn) smoother_kernel(
    const float* __restrict__ pred,
    const float* __restrict__ bias,
    float* __restrict__ out)
{
    const int c  = threadIdx.x;      // channel 0..127
    const int s  = blockIdx.x;       // T segment 0..NSEG-1
    const int b  = blockIdx.y;       // batch 0..7
    const int t0 = s * SEG;

    const float* p = pred + (size_t)b * Tn * Cn + c;   // p[t*Cn] = pred[b][t][c]
    float*       o = out  + (size_t)b * Tn * Cn + c;

    const float bv  = bias[0];
    const float inv = 1.0f / (float)Kn;

    if (s > 0 && s < NSEG - 1) {
        // ---- fast path: no reflection anywhere in [t0-250, t0+SEG+250] ----
        // init: W = sum_{k=t0-250}^{t0+250} x[k]
        const float* q = p + (t0 - Pn) * Cn;
        float w0 = 0.f, w1 = 0.f, w2 = 0.f, w3 = 0.f;
        int k = 0;
        #pragma unroll 4
        for (; k + 4 <= Kn; k += 4) {
            w0 += q[(k + 0) * Cn];
            w1 += q[(k + 1) * Cn];
            w2 += q[(k + 2) * Cn];
            w3 += q[(k + 3) * Cn];
        }
        float W = (w0 + w1) + (w2 + w3);
        for (; k < Kn; k++) W += q[k * Cn];

        const float* lead  = p + (t0 + Pn + 1) * Cn;   // x[t+251]
        const float* trail = p + (t0 - Pn) * Cn;       // x[t-250]
        const float* mid   = p + t0 * Cn;              // x[t]
        float*       op    = o + t0 * Cn;

        #pragma unroll 8
        for (int i = 0; i < SEG; i++) {
            float m = mid[i * Cn];
            op[i * Cn] = fmaxf(m, (W + bv) * inv);
            W += lead[i * Cn] - trail[i * Cn];
        }
    } else {
        // ---- boundary path: s == 0 or s == NSEG-1, use reflected indices ----
        float W = 0.f;
        for (int k = t0 - Pn; k <= t0 + Pn; k++)
            W += p[refl(k) * Cn];

        for (int i = 0; i < SEG; i++) {
            int t = t0 + i;
            float m = p[t * Cn];
            o[t * Cn] = fmaxf(m, (W + bv) * inv);
            W += p[refl(t + Pn + 1) * Cn] - p[refl(t - Pn) * Cn];
        }
    }
}

extern "C" void kernel_launch(void* const* d_in, const int* in_sizes, int n_in,
                              void* d_out, int out_size)
{
    const float* pred = (const float*)d_in[0];   // [8, 16384, 128] fp32
    const float* bias = (const float*)d_in[1];   // [1] fp32
    float*       out  = (float*)d_out;           // [8, 16384, 128] fp32

    (void)in_sizes; (void)n_in; (void)out_size;

    dim3 grid(NSEG, Bn);   // 64 x 8 = 512 blocks
    dim3 block(Cn);        // 128 threads, one per channel
    smoother_kernel<<<grid, block>>>(pred, bias, out);
}

// round 5
// speedup vs baseline: 1.1032x; 1.1032x over previous
#include <cuda_runtime.h>

// Smoother: out = max(pred, (moving_sum_501(reflect_pad_T(pred)) + bias) / 501)
// pred: [B=8, T=16384, C=128] fp32, bias: [1] fp32, out: same shape.
//
// R4: same float4 design as R3, with the fast-path guard FIXED:
// fast path only when the full window [t0-250, t0+SEG+250] fits in [0, T-1],
// i.e. t0 >= P and t0 + SEG + P + 1 <= T  (s in [2, 125] for SEG=128).
// R3's guard (s>0 && s<NSEG-1) was valid only for SEG=256 and let s=1/s=126
// read unreflected out-of-window rows -> rel_err 2.6e-3.

#define Bn   8
#define Tn   16384
#define C4   32            // 128 channels / 4 per float4
#define Kn   501
#define Pn   250
#define SEG  128
#define NSEG (Tn / SEG)    // 128

__device__ __forceinline__ int refl(int k) {
    if (k < 0) k = -k;
    if (k >= Tn) k = 2 * Tn - 2 - k;
    return k;
}

__device__ __forceinline__ void acc4(float4& a, const float4 v) {
    a.x += v.x; a.y += v.y; a.z += v.z; a.w += v.w;
}

__global__ void __launch_bounds__(32) smoother_kernel(
    const float4* __restrict__ pred,
    const float*  __restrict__ bias,
    float4*       __restrict__ out)
{
    const int c  = threadIdx.x;     // float4 channel group 0..31
    const int s  = blockIdx.x;      // T segment 0..NSEG-1
    const int b  = blockIdx.y;      // batch 0..7
    const int t0 = s * SEG;

    const float4* p = pred + (size_t)b * Tn * C4 + c;   // p[t*C4] = pred[b][t][4c..4c+3]
    float4*       o = out  + (size_t)b * Tn * C4 + c;

    const float bv  = bias[0];
    const float inv = 1.0f / (float)Kn;

    float4 W;

    // Fast path iff the entire sliding-window footprint stays in-bounds:
    //   lowest index touched:  t0 - Pn            >= 0
    //   highest index touched: t0 + SEG - 1 + Pn + 1 <= Tn - 1
    const bool fast = (t0 >= Pn) && (t0 + SEG + Pn + 1 <= Tn);

    if (fast) {
        // ---- fast path: no reflection anywhere in the footprint ----
        const float4* q = p + (t0 - Pn) * C4;
        float4 w0 = make_float4(0.f, 0.f, 0.f, 0.f);
        float4 w1 = make_float4(0.f, 0.f, 0.f, 0.f);
        float4 w2 = make_float4(0.f, 0.f, 0.f, 0.f);
        float4 w3 = make_float4(0.f, 0.f, 0.f, 0.f);
        int k = 0;
        #pragma unroll 2
        for (; k + 4 <= Kn; k += 4) {
            acc4(w0, q[(k + 0) * C4]);
            acc4(w1, q[(k + 1) * C4]);
            acc4(w2, q[(k + 2) * C4]);
            acc4(w3, q[(k + 3) * C4]);
        }
        for (; k < Kn; k++) acc4(w0, q[k * C4]);
        W.x = (w0.x + w1.x) + (w2.x + w3.x);
        W.y = (w0.y + w1.y) + (w2.y + w3.y);
        W.z = (w0.z + w1.z) + (w2.z + w3.z);
        W.w = (w0.w + w1.w) + (w2.w + w3.w);

        const float4* lead  = p + (t0 + Pn + 1) * C4;   // x[t+251]
        const float4* trail = p + (t0 - Pn) * C4;       // x[t-250]
        const float4* mid   = p + t0 * C4;              // x[t]
        float4*       op    = o + t0 * C4;

        #pragma unroll 8
        for (int i = 0; i < SEG; i++) {
            float4 m = mid[i * C4];
            float4 r;
            r.x = fmaxf(m.x, (W.x + bv) * inv);
            r.y = fmaxf(m.y, (W.y + bv) * inv);
            r.z = fmaxf(m.z, (W.z + bv) * inv);
            r.w = fmaxf(m.w, (W.w + bv) * inv);
            op[i * C4] = r;
            float4 l = lead[i * C4];
            float4 t = trail[i * C4];
            W.x += l.x - t.x;
            W.y += l.y - t.y;
            W.z += l.z - t.z;
            W.w += l.w - t.w;
        }
    } else {
        // ---- boundary path: reflected indices throughout ----
        W = make_float4(0.f, 0.f, 0.f, 0.f);
        for (int k = t0 - Pn; k <= t0 + Pn; k++)
            acc4(W, p[refl(k) * C4]);

        for (int i = 0; i < SEG; i++) {
            int t = t0 + i;
            float4 m = p[t * C4];
            float4 r;
            r.x = fmaxf(m.x, (W.x + bv) * inv);
            r.y = fmaxf(m.y, (W.y + bv) * inv);
            r.z = fmaxf(m.z, (W.z + bv) * inv);
            r.w = fmaxf(m.w, (W.w + bv) * inv);
            o[t * C4] = r;
            float4 l  = p[refl(t + Pn + 1) * C4];
            float4 tr = p[refl(t - Pn) * C4];
            W.x += l.x - tr.x;
            W.y += l.y - tr.y;
            W.z += l.z - tr.z;
            W.w += l.w - tr.w;
        }
    }
}

extern "C" void kernel_launch(void* const* d_in, const int* in_sizes, int n_in,
                              void* d_out, int out_size)
{
    const float4* pred = (const float4*)d_in[0];   // [8, 16384, 128] fp32
    const float*  bias = (const float*)d_in[1];    // [1] fp32
    float4*       out  = (float4*)d_out;

    (void)in_sizes; (void)n_in; (void)out_size;

    dim3 grid(NSEG, Bn);   // 128 x 8 = 1024 single-warp blocks
    dim3 block(32);        // one warp: 32 float4 lanes = 128 channels
    smoother_kernel<<<grid, block>>>(pred, bias, out);
}